// round 2
// baseline (speedup 1.0000x reference)
#include <cuda_runtime.h>
#include <math.h>
#include <stdint.h>

#define BB 4
#define CC 64
#define NP 8192
#define OO 128
#define KNN 20

// ---------------- device scratch ----------------
__device__ float g_xt[(size_t)BB * NP * CC];        // x transposed: [b][n][c]
__device__ float g_xx[BB * NP];                     // squared norms
__device__ float g_uvq[(size_t)BB * NP * 256];      // [b][n][ U(64) | V(64) | Q(128) ]
__device__ int   g_idx[(size_t)BB * NP * KNN];      // top-20 neighbor indices

__device__ __forceinline__ void ffma2(unsigned long long& d,
                                      unsigned long long a,
                                      unsigned long long b) {
    asm("fma.rn.f32x2 %0, %1, %2, %0;" : "+l"(d) : "l"(a), "l"(b));
}

// ---------------- K0: transpose x (B,C,N) -> xt (B,N,C) ----------------
__global__ void k_transpose(const float* __restrict__ x) {
    __shared__ float tile[32][33];
    int b  = blockIdx.z;
    int c0 = blockIdx.y * 32;
    int n0 = blockIdx.x * 32;
    int tx = threadIdx.x, ty = threadIdx.y;   // 32 x 8
#pragma unroll
    for (int yy = 0; yy < 32; yy += 8)
        tile[ty + yy][tx] = x[((size_t)b * CC + c0 + ty + yy) * NP + n0 + tx];
    __syncthreads();
#pragma unroll
    for (int yy = 0; yy < 32; yy += 8)
        g_xt[((size_t)b * NP + n0 + ty + yy) * CC + c0 + tx] = tile[tx][ty + yy];
}

// ---------------- K0b: squared norms ----------------
__global__ void k_norm() {
    int p = blockIdx.x * blockDim.x + threadIdx.x;
    const float4* v = (const float4*)&g_xt[(size_t)p * CC];
    float s = 0.f;
#pragma unroll
    for (int i = 0; i < 16; i++) {
        float4 q = v[i];
        s += q.x * q.x + q.y * q.y + q.z * q.z + q.w * q.w;
    }
    g_xx[p] = s;
}

// ---------------- K1: precompute U, V, Q per point ----------------
__global__ __launch_bounds__(256) void k_uvq(const float* __restrict__ W1,
                                             const float* __restrict__ W2) {
    __shared__ float xts[16][64];
    int p0 = blockIdx.x * 16;
    int o  = threadIdx.x;
    for (int s = threadIdx.x; s < 16 * 64; s += 256)
        xts[s >> 6][s & 63] = g_xt[(size_t)p0 * 64 + s];

    float4 wr[16];
    if (o < 64) {
        const float* r = W1 + o * 128;
#pragma unroll
        for (int i = 0; i < 16; i++)
            wr[i] = make_float4(r[4*i], r[4*i+1], r[4*i+2], r[4*i+3]);
    } else if (o < 128) {
        const float* r = W1 + (o - 64) * 128;
#pragma unroll
        for (int i = 0; i < 16; i++)
            wr[i] = make_float4(r[64+4*i]-r[4*i], r[65+4*i]-r[4*i+1],
                                r[66+4*i]-r[4*i+2], r[67+4*i]-r[4*i+3]);
    } else {
        const float* r = W2 + (o - 128) * 128;
#pragma unroll
        for (int i = 0; i < 16; i++)
            wr[i] = make_float4(r[64+4*i]-r[4*i], r[65+4*i]-r[4*i+1],
                                r[66+4*i]-r[4*i+2], r[67+4*i]-r[4*i+3]);
    }
    __syncthreads();

    float acc[16];
#pragma unroll
    for (int p = 0; p < 16; p++) acc[p] = 0.f;
#pragma unroll
    for (int c4 = 0; c4 < 16; c4++) {
        float4 w = wr[c4];
#pragma unroll
        for (int p = 0; p < 16; p++) {
            float4 xv = *(const float4*)&xts[p][c4 * 4];
            acc[p] += w.x * xv.x + w.y * xv.y + w.z * xv.z + w.w * xv.w;
        }
    }
#pragma unroll
    for (int p = 0; p < 16; p++)
        g_uvq[((size_t)p0 + p) * 256 + o] = acc[p];
}

// ---------------- K2: kNN top-20, f32x2 packed distance GEMM ----------------
// Selection value v(i,j) = 2*dot(xi,xj) - xx_j  (xx_i is row-constant: rank-invariant)
#define TI 128
#define TJ 64
// smem float offsets
#define OXID 0                         // 64 x 260  (i duplicated {v,v}, stride 260)
#define OXJ  (64*260)                  // 64 x 68
#define ODS  (OXJ + 64*68)             // 128 x 33  (distance half-tile)
#define OXXJ (ODS + 128*33)            // 64
#define SMEMF (OXXJ + 64)
#define KNN_SMEM_BYTES (SMEMF * 4)

__global__ void __launch_bounds__(256) k_knn() {
    extern __shared__ float sm[];
    float* xid = sm + OXID;
    float* xj  = sm + OXJ;
    float* Ds  = sm + ODS;
    float* xxj = sm + OXXJ;

    int b   = blockIdx.y;
    int i0  = blockIdx.x * TI;
    int tid = threadIdx.x;
    int ty  = tid >> 3;   // 0..31 : rows 4ty..4ty+3
    int tx  = tid & 7;    // 0..7  : cols 8tx..8tx+7
    size_t base = (size_t)b * NP;

    // Load i-tile duplicated: xid[c][2i] = xid[c][2i+1] = xt[i][c]
    for (int s = tid; s < TI * 64; s += 256) {
        int i = s >> 6, c = s & 63;
        float v = g_xt[(base + i0 + i) * 64 + c];
        *(float2*)&xid[c * 260 + 2 * i] = make_float2(v, v);
    }

    float bv[KNN]; int bi[KNN];
    float minv = -3.4e38f; int minp = 0;
#pragma unroll
    for (int t = 0; t < KNN; t++) { bv[t] = -3.4e38f; bi[t] = 0; }

    const float* pja = xj + tx * 8;
    const float* pia = xid + ty * 8;
    int hsel = tx >> 2;

    for (int jt = 0; jt < NP; jt += TJ) {
        // load j-tile (prev iteration ended with __syncthreads)
        for (int s = tid; s < TJ * 64; s += 256) {
            int r = s >> 6, c = s & 63;
            xj[c * 68 + r] = g_xt[(base + jt + r) * 64 + c];
        }
        if (tid < TJ) xxj[tid] = g_xx[base + jt + tid];
        __syncthreads();

        unsigned long long acc[4][4];
#pragma unroll
        for (int i = 0; i < 4; i++)
#pragma unroll
            for (int p = 0; p < 4; p++) acc[i][p] = 0ULL;

#pragma unroll 16
        for (int c = 0; c < 64; c++) {
            ulonglong2 b0 = *(const ulonglong2*)(pja + c * 68);
            ulonglong2 b1 = *(const ulonglong2*)(pja + c * 68 + 4);
            ulonglong2 a0 = *(const ulonglong2*)(pia + c * 260);
            ulonglong2 a1 = *(const ulonglong2*)(pia + c * 260 + 4);
            unsigned long long ap0 = a0.x, ap1 = a0.y, ap2 = a1.x, ap3 = a1.y;
            unsigned long long bp0 = b0.x, bp1 = b0.y, bp2 = b1.x, bp3 = b1.y;
            ffma2(acc[0][0], ap0, bp0); ffma2(acc[0][1], ap0, bp1);
            ffma2(acc[0][2], ap0, bp2); ffma2(acc[0][3], ap0, bp3);
            ffma2(acc[1][0], ap1, bp0); ffma2(acc[1][1], ap1, bp1);
            ffma2(acc[1][2], ap1, bp2); ffma2(acc[1][3], ap1, bp3);
            ffma2(acc[2][0], ap2, bp0); ffma2(acc[2][1], ap2, bp1);
            ffma2(acc[2][2], ap2, bp2); ffma2(acc[2][3], ap2, bp3);
            ffma2(acc[3][0], ap3, bp0); ffma2(acc[3][1], ap3, bp1);
            ffma2(acc[3][2], ap3, bp2); ffma2(acc[3][3], ap3, bp3);
        }

        // Two j-halves: write 128x32 distances, scan, repeat
#pragma unroll
        for (int h = 0; h < 2; h++) {
            if (hsel == h) {
#pragma unroll
                for (int i = 0; i < 4; i++) {
                    int row = 4 * ty + i;
#pragma unroll
                    for (int p = 0; p < 4; p++) {
                        int jc = 8 * tx + 2 * p;          // 0..63 tile-local
                        float lo = __uint_as_float((unsigned)acc[i][p]);
                        float hi = __uint_as_float((unsigned)(acc[i][p] >> 32));
                        Ds[row * 33 + jc - 32 * h]     = 2.f * lo - xxj[jc];
                        Ds[row * 33 + jc + 1 - 32 * h] = 2.f * hi - xxj[jc + 1];
                    }
                }
            }
            __syncthreads();
            if (tid < TI) {
                int jb = jt + 32 * h;
                for (int j = 0; j < 32; j++) {
                    float v = Ds[tid * 33 + j];
                    if (v > minv) {
                        bv[minp] = v; bi[minp] = jb + j;
                        minv = bv[0]; minp = 0;
#pragma unroll
                        for (int t = 1; t < KNN; t++)
                            if (bv[t] < minv) { minv = bv[t]; minp = t; }
                    }
                }
            }
            __syncthreads();
        }
    }

    if (tid < TI) {
#pragma unroll
        for (int t = 0; t < KNN; t++)
            g_idx[(base + i0 + tid) * KNN + t] = bi[t];
    }
}

// ---------------- K3: fused gather + softmax gate + output GEMM ----------------
__global__ __launch_bounds__(256) void k_fuse(const float* __restrict__ W2,
                                              float* __restrict__ out) {
    __shared__ float w2as[64 * 128];
    __shared__ float t_s[16][64];
    __shared__ int   idxs[16][KNN];

    int blk = blockIdx.x;
    int b   = blk >> 9;
    int n0  = (blk & 511) * 16;
    int tid = threadIdx.x;
    size_t base = (size_t)b * NP;

    for (int s = tid; s < 8192; s += 256) {
        int o = s >> 6, c = s & 63;
        w2as[c * 128 + o] = W2[o * 128 + c];
    }
    for (int s = tid; s < 16 * KNN; s += 256)
        idxs[s / KNN][s % KNN] = g_idx[(base + n0) * KNN + s];
    __syncthreads();

    for (int pass = 0; pass < 4; pass++) {
        int pt = pass * 4 + (tid >> 6);
        int d  = tid & 63;
        float vv = g_uvq[(base + n0 + pt) * 256 + 64 + d];
        float h[KNN];
#pragma unroll
        for (int k = 0; k < KNN; k++) {
            int j = idxs[pt][k];
            h[k] = g_uvq[(base + j) * 256 + d] + vv;
        }
        float m = h[0];
#pragma unroll
        for (int k = 1; k < KNN; k++) m = fmaxf(m, h[k]);
        float S = 0.f, ws = 0.f;
#pragma unroll
        for (int k = 0; k < KNN; k++) {
            float e = __expf(h[k] - m);
            S += e;
            int j = idxs[pt][k];
            ws += g_xt[(base + j) * 64 + d] * e;
        }
        t_s[pt][d] = ws / S;
    }
    __syncthreads();

    int o = tid & 127, g = tid >> 7;
    float acc[8];
#pragma unroll
    for (int p = 0; p < 8; p++)
        acc[p] = g_uvq[(base + n0 + g * 8 + p) * 256 + 128 + o];
#pragma unroll 8
    for (int c = 0; c < 64; c++) {
        float w = w2as[c * 128 + o];
#pragma unroll
        for (int p = 0; p < 8; p++) acc[p] += w * t_s[g * 8 + p][c];
    }
    float* op = out + ((size_t)b * OO + o) * NP + n0 + g * 8;
    *(float4*)op       = make_float4(acc[0], acc[1], acc[2], acc[3]);
    *(float4*)(op + 4) = make_float4(acc[4], acc[5], acc[6], acc[7]);
}

// ---------------- launch ----------------
extern "C" void kernel_launch(void* const* d_in, const int* in_sizes, int n_in,
                              void* d_out, int out_size) {
    const float* x  = (const float*)d_in[0];
    const float* W1 = (const float*)d_in[1];
    const float* W2 = (const float*)d_in[2];
    float* out = (float*)d_out;

    cudaFuncSetAttribute(k_knn, cudaFuncAttributeMaxDynamicSharedMemorySize,
                         KNN_SMEM_BYTES);

    k_transpose<<<dim3(NP / 32, CC / 32, BB), dim3(32, 8)>>>(x);
    k_norm<<<(BB * NP) / 256, 256>>>();
    k_uvq<<<(BB * NP) / 16, 256>>>(W1, W2);
    k_knn<<<dim3(NP / TI, BB), 256, KNN_SMEM_BYTES>>>();
    k_fuse<<<(BB * NP) / 16, 256>>>(W2, out);
}